// round 1
// baseline (speedup 1.0000x reference)
#include <cuda_runtime.h>

#define BSZ 4
#define SEQ 256
#define DIM 128
#define HID 128
#define DFF 512
#define MROWS (BSZ*SEQ)   // 1024

// ---------------- scratch (device globals; no allocations) ----------------
__device__ float g_p1 [MROWS*DIM];
__device__ float g_T1A[MROWS*HID];
__device__ float g_T1B[MROWS*HID];
__device__ float g_T2A[MROWS*HID];
__device__ float g_T2B[MROWS*HID];
__device__ float g_logits[BSZ*SEQ*SEQ];
__device__ float g_ctx[MROWS*DIM];
__device__ float g_tmp[MROWS*DIM];
__device__ float g_out1[MROWS*DIM];
__device__ float g_pq [MROWS*DIM];
__device__ float g_pk [MROWS*DIM];
__device__ float g_out2[MROWS*DIM];
__device__ float g_fh [MROWS*DFF];

// ---------------- generic SGEMM: C = A[M,K] @ B[K,N] (+bias, relu), batched strides ----
// tiles: BM=32, BN=32, BK=32; 256 threads; 2x2 micro-tile per thread.
__global__ void sgemm_kernel(const float* __restrict__ A, const float* __restrict__ B,
                             const float* __restrict__ bias, float* __restrict__ C,
                             int M, int N, int K, int relu,
                             long sA, long sB, long sC)
{
    __shared__ float As[32][34];   // [k][m]
    __shared__ float Bs[32][34];   // [k][n]
    const float* Ab = A + (long)blockIdx.z * sA;
    const float* Bb = B + (long)blockIdx.z * sB;
    float* Cb = C + (long)blockIdx.z * sC;
    int m0 = blockIdx.y * 32, n0 = blockIdx.x * 32;
    int tid = threadIdx.x;
    int tx = tid & 15, ty = tid >> 4;
    float acc00 = 0.f, acc01 = 0.f, acc10 = 0.f, acc11 = 0.f;

    for (int k0 = 0; k0 < K; k0 += 32) {
        #pragma unroll
        for (int i = 0; i < 4; i++) {
            int idx = tid + i * 256;           // 0..1023
            int ka = idx & 31, ma = idx >> 5;  // A: coalesced over k
            As[ka][ma] = Ab[(long)(m0 + ma) * K + k0 + ka];
            int nb = idx & 31, kb = idx >> 5;  // B: coalesced over n
            Bs[kb][nb] = Bb[(long)(k0 + kb) * N + n0 + nb];
        }
        __syncthreads();
        #pragma unroll
        for (int kk = 0; kk < 32; kk++) {
            float2 a = *(const float2*)&As[kk][ty * 2];
            float2 b = *(const float2*)&Bs[kk][tx * 2];
            acc00 += a.x * b.x; acc01 += a.x * b.y;
            acc10 += a.y * b.x; acc11 += a.y * b.y;
        }
        __syncthreads();
    }
    int m = m0 + ty * 2, n = n0 + tx * 2;
    float bb0 = bias ? bias[n]     : 0.f;
    float bb1 = bias ? bias[n + 1] : 0.f;
    float v00 = acc00 + bb0, v01 = acc01 + bb1;
    float v10 = acc10 + bb0, v11 = acc11 + bb1;
    if (relu) {
        v00 = fmaxf(v00, 0.f); v01 = fmaxf(v01, 0.f);
        v10 = fmaxf(v10, 0.f); v11 = fmaxf(v11, 0.f);
    }
    Cb[(long)m * N + n]           = v00;
    Cb[(long)m * N + n + 1]       = v01;
    Cb[(long)(m + 1) * N + n]     = v10;
    Cb[(long)(m + 1) * N + n + 1] = v11;
}

// ---------------- pairwise similarity (both symmetric terms fused) -----------------
// logits[b,q,k] = sum_h relu(T1A[q,h]+T1B[k,h])*W2[h]
//              + sum_h relu(T2A[k,h]+T2B[q,h])*W2[h] + 2*b2[0]
// (b1 is pre-folded into T1A and T2A by the producing GEMMs)
// tile: 32 q-rows x 64 k-cols; H chunked by 32; 256 threads, 2x4 micro.
__global__ void sim_kernel(const float* __restrict__ T1A, const float* __restrict__ T1B,
                           const float* __restrict__ T2A, const float* __restrict__ T2B,
                           const float* __restrict__ W2,  const float* __restrict__ b2p,
                           float* __restrict__ logits)
{
    __shared__ float s1a[32][34];  // T1A q-rows, [h][q]
    __shared__ float s2b[32][34];  // T2B q-rows, [h][q]
    __shared__ float s1b[32][68];  // T1B k-rows, [h][k]
    __shared__ float s2a[32][68];  // T2A k-rows, [h][k]
    __shared__ float sw[32];

    int b  = blockIdx.z;
    int q0 = blockIdx.y * 32;
    int k0 = blockIdx.x * 64;
    const float* p1a = T1A + ((long)b * SEQ + q0) * HID;
    const float* p2b = T2B + ((long)b * SEQ + q0) * HID;
    const float* p1b = T1B + ((long)b * SEQ + k0) * HID;
    const float* p2a = T2A + ((long)b * SEQ + k0) * HID;
    int tid = threadIdx.x;
    int tx = tid & 15, ty = tid >> 4;
    float acc[2][4] = {};

    for (int h0 = 0; h0 < HID; h0 += 32) {
        #pragma unroll
        for (int i = 0; i < 4; i++) {          // q-side: 32 rows x 32 h
            int idx = tid + i * 256;
            int r = idx >> 5, h = idx & 31;
            s1a[h][r] = p1a[(long)r * HID + h0 + h];
            s2b[h][r] = p2b[(long)r * HID + h0 + h];
        }
        #pragma unroll
        for (int i = 0; i < 8; i++) {          // k-side: 64 rows x 32 h
            int idx = tid + i * 256;
            int r = idx >> 5, h = idx & 31;
            s1b[h][r] = p1b[(long)r * HID + h0 + h];
            s2a[h][r] = p2a[(long)r * HID + h0 + h];
        }
        if (tid < 32) sw[tid] = W2[h0 + tid];
        __syncthreads();

        #pragma unroll 8
        for (int h = 0; h < 32; h++) {
            float w = sw[h];
            float2 a1r = *(const float2*)&s1a[h][ty * 2];
            float2 b2r = *(const float2*)&s2b[h][ty * 2];
            float4 b1r = *(const float4*)&s1b[h][tx * 4];
            float4 a2r = *(const float4*)&s2a[h][tx * 4];
            float a1v[2] = {a1r.x, a1r.y};
            float b2v[2] = {b2r.x, b2r.y};
            float b1v[4] = {b1r.x, b1r.y, b1r.z, b1r.w};
            float a2v[4] = {a2r.x, a2r.y, a2r.z, a2r.w};
            #pragma unroll
            for (int i = 0; i < 2; i++) {
                #pragma unroll
                for (int j = 0; j < 4; j++) {
                    float t1 = a1v[i] + b1v[j];
                    acc[i][j] += fmaxf(t1, 0.f) * w;
                    float t2 = a2v[j] + b2v[i];
                    acc[i][j] += fmaxf(t2, 0.f) * w;
                }
            }
        }
        __syncthreads();
    }

    float c2 = 2.f * b2p[0];
    #pragma unroll
    for (int i = 0; i < 2; i++) {
        int q = q0 + ty * 2 + i;
        #pragma unroll
        for (int j = 0; j < 4; j++) {
            int k = k0 + tx * 4 + j;
            logits[((long)b * SEQ + q) * SEQ + k] = acc[i][j] + c2;
        }
    }
}

// ---------------- masked softmax over last axis (in-place) -----------------
__global__ void softmax_kernel(float* __restrict__ logits, const float* __restrict__ mask)
{
    int q = blockIdx.x, b = blockIdx.y;
    long off = ((long)b * SEQ + q) * SEQ;
    int t = threadIdx.x;
    __shared__ float red[8];

    float x = logits[off + t] + mask[off + t] * (-1e9f);
    float m = x;
    #pragma unroll
    for (int o = 16; o; o >>= 1) m = fmaxf(m, __shfl_xor_sync(0xffffffffu, m, o));
    if ((t & 31) == 0) red[t >> 5] = m;
    __syncthreads();
    m = red[0];
    #pragma unroll
    for (int i = 1; i < 8; i++) m = fmaxf(m, red[i]);

    float e = __expf(x - m);
    float s = e;
    #pragma unroll
    for (int o = 16; o; o >>= 1) s += __shfl_xor_sync(0xffffffffu, s, o);
    __syncthreads();
    if ((t & 31) == 0) red[t >> 5] = s;
    __syncthreads();
    s = red[0] + red[1] + red[2] + red[3] + red[4] + red[5] + red[6] + red[7];
    logits[off + t] = e / s;
}

// ---------------- fused residual add + LayerNorm (warp per 128-row) --------
__global__ void add_ln_kernel(const float* __restrict__ a, const float* __restrict__ r,
                              const float* __restrict__ g, const float* __restrict__ be,
                              float* __restrict__ out)
{
    int row  = blockIdx.x * 8 + (threadIdx.x >> 5);
    int lane = threadIdx.x & 31;
    long base = (long)row * DIM + lane * 4;
    float4 av = *(const float4*)(a + base);
    float4 rv = *(const float4*)(r + base);
    float v[4] = {av.x + rv.x, av.y + rv.y, av.z + rv.z, av.w + rv.w};
    float s = v[0] + v[1] + v[2] + v[3];
    #pragma unroll
    for (int o = 16; o; o >>= 1) s += __shfl_xor_sync(0xffffffffu, s, o);
    float mean = s * (1.f / DIM);
    float vs = 0.f;
    #pragma unroll
    for (int j = 0; j < 4; j++) { float d = v[j] - mean; vs += d * d; }
    #pragma unroll
    for (int o = 16; o; o >>= 1) vs += __shfl_xor_sync(0xffffffffu, vs, o);
    float inv = rsqrtf(vs * (1.f / DIM) + 1e-6f);
    float4 gv = *(const float4*)(g + lane * 4);
    float4 bv = *(const float4*)(be + lane * 4);
    float4 o4;
    o4.x = (v[0] - mean) * inv * gv.x + bv.x;
    o4.y = (v[1] - mean) * inv * gv.y + bv.y;
    o4.z = (v[2] - mean) * inv * gv.z + bv.z;
    o4.w = (v[3] - mean) * inv * gv.w + bv.w;
    *(float4*)(out + base) = o4;
}

// ---------------- host orchestration ----------------
static inline void G(const float* A, const float* B, const float* bias, float* C,
                     int M, int N, int K, int relu, int batch,
                     long sA, long sB, long sC)
{
    dim3 grid(N / 32, M / 32, batch);
    sgemm_kernel<<<grid, 256>>>(A, B, bias, C, M, N, K, relu, sA, sB, sC);
}

extern "C" void kernel_launch(void* const* d_in, const int* in_sizes, int n_in,
                              void* d_out, int out_size)
{
    (void)in_sizes; (void)n_in; (void)out_size;
    const float* x    = (const float*)d_in[0];
    const float* enc  = (const float*)d_in[1];
    const float* cmsk = (const float*)d_in[2];
    const float* dmsk = (const float*)d_in[3];
    const float* W1q  = (const float*)d_in[4];
    const float* W1k  = (const float*)d_in[5];
    const float* b1   = (const float*)d_in[6];
    const float* W2   = (const float*)d_in[7];
    const float* b2   = (const float*)d_in[8];
    const float* Ww1  = (const float*)d_in[9];
    const float* bw1  = (const float*)d_in[10];
    const float* Wd1  = (const float*)d_in[11];
    const float* bd1  = (const float*)d_in[12];
    const float* Ww2  = (const float*)d_in[13];
    const float* bw2  = (const float*)d_in[14];
    const float* Wd2  = (const float*)d_in[15];
    const float* bd2  = (const float*)d_in[16];
    const float* Wf1  = (const float*)d_in[17];
    const float* bf1  = (const float*)d_in[18];
    const float* Wf2  = (const float*)d_in[19];
    const float* bf2  = (const float*)d_in[20];
    const float* ln1g = (const float*)d_in[21];
    const float* ln1b = (const float*)d_in[22];
    const float* ln2g = (const float*)d_in[23];
    const float* ln2b = (const float*)d_in[24];
    const float* ln3g = (const float*)d_in[25];
    const float* ln3b = (const float*)d_in[26];
    float* out = (float*)d_out;

    float *p1, *t1a, *t1b, *t2a, *t2b, *lg, *ctx, *tmp, *o1, *pq, *pk, *o2, *fh;
    cudaGetSymbolAddress((void**)&p1,  g_p1);
    cudaGetSymbolAddress((void**)&t1a, g_T1A);
    cudaGetSymbolAddress((void**)&t1b, g_T1B);
    cudaGetSymbolAddress((void**)&t2a, g_T2A);
    cudaGetSymbolAddress((void**)&t2b, g_T2B);
    cudaGetSymbolAddress((void**)&lg,  g_logits);
    cudaGetSymbolAddress((void**)&ctx, g_ctx);
    cudaGetSymbolAddress((void**)&tmp, g_tmp);
    cudaGetSymbolAddress((void**)&o1,  g_out1);
    cudaGetSymbolAddress((void**)&pq,  g_pq);
    cudaGetSymbolAddress((void**)&pk,  g_pk);
    cudaGetSymbolAddress((void**)&o2,  g_out2);
    cudaGetSymbolAddress((void**)&fh,  g_fh);

    dim3 simGrid(SEQ / 64, SEQ / 32, BSZ);
    dim3 smGrid(SEQ, BSZ);

    // ---- self-attention block (q = k = v = x @ Ww1 + bw1) ----
    G(x,  Ww1, bw1, p1,  MROWS, DIM, DIM, 0, 1, 0, 0, 0);
    G(p1, W1q, b1,  t1a, MROWS, HID, DIM, 0, 1, 0, 0, 0);  // qa + b1
    G(p1, W1k, 0,   t1b, MROWS, HID, DIM, 0, 1, 0, 0, 0);  // kb
    sim_kernel<<<simGrid, 256>>>(t1a, t1b, t1a, t1b, W2, b2, lg);
    softmax_kernel<<<smGrid, 256>>>(lg, cmsk);
    G(lg, p1, 0, ctx, SEQ, DIM, SEQ, 0, BSZ,
      (long)SEQ * SEQ, (long)SEQ * DIM, (long)SEQ * DIM);   // attn @ v
    G(ctx, Wd1, bd1, tmp, MROWS, DIM, DIM, 0, 1, 0, 0, 0);
    add_ln_kernel<<<MROWS / 8, 256>>>(tmp, x, ln1g, ln1b, o1);

    // ---- cross-attention block (q = out1 proj, k = v = enc proj) ----
    G(o1,  Ww2, bw2, pq,  MROWS, DIM, DIM, 0, 1, 0, 0, 0);
    G(enc, Ww2, bw2, pk,  MROWS, DIM, DIM, 0, 1, 0, 0, 0);
    G(pq,  W1q, b1,  t1a, MROWS, HID, DIM, 0, 1, 0, 0, 0);  // qa + b1
    G(pk,  W1k, 0,   t1b, MROWS, HID, DIM, 0, 1, 0, 0, 0);  // kb
    G(pk,  W1q, b1,  t2a, MROWS, HID, DIM, 0, 1, 0, 0, 0);  // ka + b1
    G(pq,  W1k, 0,   t2b, MROWS, HID, DIM, 0, 1, 0, 0, 0);  // qb
    sim_kernel<<<simGrid, 256>>>(t1a, t1b, t2a, t2b, W2, b2, lg);
    softmax_kernel<<<smGrid, 256>>>(lg, dmsk);
    G(lg, pk, 0, ctx, SEQ, DIM, SEQ, 0, BSZ,
      (long)SEQ * SEQ, (long)SEQ * DIM, (long)SEQ * DIM);
    G(ctx, Wd2, bd2, tmp, MROWS, DIM, DIM, 0, 1, 0, 0, 0);
    add_ln_kernel<<<MROWS / 8, 256>>>(tmp, o1, ln2g, ln2b, o2);

    // ---- FFN block ----
    G(o2, Wf1, bf1, fh,  MROWS, DFF, DIM, 1, 1, 0, 0, 0);   // relu fused
    G(fh, Wf2, bf2, tmp, MROWS, DIM, DFF, 0, 1, 0, 0, 0);
    add_ln_kernel<<<MROWS / 8, 256>>>(tmp, o2, ln3g, ln3b, out);
}